// round 8
// baseline (speedup 1.0000x reference)
#include <cuda_runtime.h>

// sLSTM: B=256, T=512, D=8, H=120, L=4, NH=8, HD=15
// R7 per-warp scan (ring h-exchange, folded log2e/0.5, no per-step syncs)
// restructured for 2 warps/SMSP latency hiding:
//   64 CTAs x 256 threads; warps 0-3 scan batches (0,1), warps 4-7 scan
//   batches (2,3). Independent streams interleave on each SMSP and cover
//   each other's LDS/MUFU latency. x kept as plain float in smem (64KB),
//   expanded per 64-step chunk into a small duplicated (v,v) buffer.
//   Projection: 4 batches x 64 steps = 256 tasks = 1 per thread.

#define B_ 256
#define T_ 512
#define D_ 8
#define H_ 120
#define L_ 4
#define NPAIR 60
#define ST 61              // hs row stride (ull)
#define BST (64 * ST + 1)  // hs batch stride (ull) (7810 mod 32 = 2: ok)
#define XDS 520            // xdup batch stride (ull) (1040 mod 32 = 16: ok)
#define XPS 4100           // x_plain batch stride (floats)
#define LOG2E 1.4426950408889634f

typedef unsigned long long ull;

__device__ float g_last[B_ * D_];

__device__ __forceinline__ ull f2pack(float x, float y) {
    ull r; asm("mov.b64 %0, {%1, %2};" : "=l"(r) : "f"(x), "f"(y)); return r;
}
__device__ __forceinline__ void f2unpack(ull v, float& x, float& y) {
    asm("mov.b64 {%0, %1}, %2;" : "=f"(x), "=f"(y) : "l"(v));
}
__device__ __forceinline__ ull f2fma(ull a, ull b, ull c) {
    ull d; asm("fma.rn.f32x2 %0, %1, %2, %3;" : "=l"(d) : "l"(a), "l"(b), "l"(c));
    return d;
}
__device__ __forceinline__ float tanh_ap(float x) {
    float r; asm("tanh.approx.f32 %0, %1;" : "=f"(r) : "f"(x)); return r;
}
__device__ __forceinline__ float rcp_ap(float x) {
    float r; asm("rcp.approx.f32 %0, %1;" : "=f"(r) : "f"(x)); return r;
}
__device__ __forceinline__ float ex2_ap(float x) {
    float r; asm("ex2.approx.f32 %0, %1;" : "=f"(r) : "f"(x)); return r;
}

// sLSTM cell. it/ft pre-scaled by log2e, ot pre-scaled by 0.5.
__device__ __forceinline__ float cellf(float it, float ft, float zt, float ot,
                                       float& c, float& nn, float& m) {
    float z  = tanh_ap(zt);
    float o  = fmaf(tanh_ap(ot), 0.5f, 0.5f);
    float b  = ft + m;
    float mn = fmaxf(it, b);
    float e  = ex2_ap(-fabsf(it - b));
    bool ag  = (it >= b);
    float ip = ag ? 1.f : e;
    float fp = ag ? e : 1.f;
    c  = fp * c  + ip * z;
    nn = fp * nn + ip;
    m  = mn;
    return o * c * rcp_ap(nn);
}

// shared layout (ull units unless noted):
//   xdup [4][XDS]  = 2080   chunk x, duplicated (v,v)
//   hsb  [4][BST]  = 15620  h history rings (paired)
//   wp2  [8*60]    = 480
//   bps  [8 floats]
//   xp   [4][XPS]  floats   residual/x stream (plain f32)
#define SM_XD  0
#define SM_HS  2080
#define SM_WP  (SM_HS + 4 * BST)
#define SM_BP  (SM_WP + 480)
#define SM_XP  (SM_BP + 4)
#define SM_TOT (SM_XP + (4 * XPS + 1) / 2 + 1)
#define SMEM_BYTES (SM_TOT * 8 + 16)

__global__ void __launch_bounds__(256, 1) slstm_kernel(
    const float* __restrict__ X,
    const float* __restrict__ Wi, const float* __restrict__ Wf,
    const float* __restrict__ Wz, const float* __restrict__ Wo,
    const float* __restrict__ Ri, const float* __restrict__ Rf,
    const float* __restrict__ Rz, const float* __restrict__ Ro,
    const float* __restrict__ bi, const float* __restrict__ bf,
    const float* __restrict__ bz, const float* __restrict__ bo,
    const float* __restrict__ Wp, const float* __restrict__ bp)
{
    extern __shared__ ull sm[];
    ull* xdup = sm + SM_XD;
    ull* hsb  = sm + SM_HS;
    ull* wp2  = sm + SM_WP;
    float* bps = (float*)(sm + SM_BP);
    float* xp  = (float*)(sm + SM_XP);

    const int tid  = threadIdx.x;
    const int lane = tid & 31;
    const int wid  = tid >> 5;
    const int k    = wid & 3;            // head block (pairs k+4)
    const int bsel = (wid >> 2) * 2;     // batch group: warps 0-3 -> 0, 4-7 -> 2
    const int half = (lane >> 4) & 1;
    const int bb   = bsel + half;        // batch within CTA (0..3)
    const int e    = lane & 15;
    const bool act = (e < 15);
    const int b0   = blockIdx.x * 4;
    const int ec   = act ? e : 14;
    const int slot = k * 15 + ec;

    // load input x (plain float) for 4 batches
    for (int idx = tid; idx < 4 * T_ * D_; idx += 256) {
        int bbi = idx >> 12;
        int i   = idx & 4095;
        xp[bbi * XPS + i] = X[(b0 + bbi) * (T_ * D_) + i];
    }

    #pragma unroll 1
    for (int l = 0; l < L_; l++) {
        // ---- packed weights into registers (i/f scaled log2e, o scaled .5) ----
        ull rIv[15], rFv[15], rZv[15], rOv[15];
        ull wIv[8],  wFv[8],  wZv[8],  wOv[8];
        ull bIv, bFv, bZv, bOv;
        {
            const int j0 = slot, j1 = slot + 60;
            const float* wi = Wi + l * H_ * D_;
            const float* wf = Wf + l * H_ * D_;
            const float* wz = Wz + l * H_ * D_;
            const float* wo = Wo + l * H_ * D_;
            #pragma unroll
            for (int d = 0; d < 8; d++) {
                wIv[d] = f2pack(LOG2E * wi[j0 * 8 + d], LOG2E * wi[j1 * 8 + d]);
                wFv[d] = f2pack(LOG2E * wf[j0 * 8 + d], LOG2E * wf[j1 * 8 + d]);
                wZv[d] = f2pack(wz[j0 * 8 + d], wz[j1 * 8 + d]);
                wOv[d] = f2pack(0.5f * wo[j0 * 8 + d], 0.5f * wo[j1 * 8 + d]);
            }
            const float* ri = Ri + l * 8 * 225;
            const float* rf = Rf + l * 8 * 225;
            const float* rz = Rz + l * 8 * 225;
            const float* ro = Ro + l * 8 * 225;
            #pragma unroll
            for (int d = 0; d < 15; d++) {
                int i0 = k * 225 + d * 15 + ec;
                int i1 = (k + 4) * 225 + d * 15 + ec;
                rIv[d] = f2pack(LOG2E * ri[i0], LOG2E * ri[i1]);
                rFv[d] = f2pack(LOG2E * rf[i0], LOG2E * rf[i1]);
                rZv[d] = f2pack(rz[i0], rz[i1]);
                rOv[d] = f2pack(0.5f * ro[i0], 0.5f * ro[i1]);
            }
            bIv = f2pack(LOG2E * bi[l * H_ + j0], LOG2E * bi[l * H_ + j1]);
            bFv = f2pack(LOG2E * bf[l * H_ + j0], LOG2E * bf[l * H_ + j1]);
            bZv = f2pack(bz[l * H_ + j0], bz[l * H_ + j1]);
            bOv = f2pack(0.5f * bo[l * H_ + j0], 0.5f * bo[l * H_ + j1]);
        }
        for (int idx = tid; idx < 8 * NPAIR; idx += 256) {
            int d = idx / NPAIR, p = idx - d * NPAIR;
            const float* wp = Wp + l * D_ * H_;
            wp2[idx] = f2pack(wp[d * H_ + p], wp[d * H_ + p + 60]);
        }
        if (tid < 8) bps[tid] = bp[l * D_ + tid];
        // zero each ring's "step -1" row (8 warps x 30 lanes = 4 batches x 60 slots)
        if (act)
            hsb[bb * BST + 63 * ST + slot] = 0ull;
        __syncthreads();

        float c0 = 0.f, c1 = 0.f, n0 = 0.f, n1 = 0.f, m0 = 0.f, m1 = 0.f;

        ull* __restrict__ hrow = hsb + bb * BST;
        const int hoff = k * 15;

        #pragma unroll 1
        for (int ch = 0; ch < 8; ch++) {
            const int tbase = ch * 64;
            // ---- expand this chunk's x into duplicated buffer ----
            for (int idx = tid; idx < 4 * 512; idx += 256) {
                int bbi = idx >> 9, i = idx & 511;
                float v = xp[bbi * XPS + tbase * 8 + i];
                xdup[bbi * XDS + i] = f2pack(v, v);
            }
            __syncthreads();
            // ---- scan 64 steps: warp-private ring, no per-step syncs ----
            #pragma unroll 2
            for (int tt = 0; tt < 64; tt++) {
                const int p = (tt - 1) & 63;
                ull aI = bIv, aF = bFv, aZ = bZv, aO = bOv;
                const ull* __restrict__ xr = xdup + bb * XDS + tt * 8;
                #pragma unroll
                for (int d = 0; d < 8; d++) {
                    ull xv = xr[d];
                    aI = f2fma(xv, wIv[d], aI);
                    aF = f2fma(xv, wFv[d], aF);
                    aZ = f2fma(xv, wZv[d], aZ);
                    aO = f2fma(xv, wOv[d], aO);
                }
                const ull* __restrict__ hr = hrow + p * ST + hoff;
                #pragma unroll
                for (int d = 0; d < 15; d++) {
                    ull hv = hr[d];
                    aI = f2fma(hv, rIv[d], aI);
                    aF = f2fma(hv, rFv[d], aF);
                    aZ = f2fma(hv, rZv[d], aZ);
                    aO = f2fma(hv, rOv[d], aO);
                }
                float itx, ity, ftx, fty, ztx, zty, otx, oty;
                f2unpack(aI, itx, ity); f2unpack(aF, ftx, fty);
                f2unpack(aZ, ztx, zty); f2unpack(aO, otx, oty);
                float h0 = cellf(itx, ftx, ztx, otx, c0, n0, m0);
                float h1 = cellf(ity, fty, zty, oty, c1, n1, m1);
                if (act)
                    hrow[tt * ST + slot] = f2pack(h0, h1);
            }
            __syncthreads();
            // ---- projection: x[t] += hs[t] @ Wp^T + bp; 256 tasks, 1/thread ----
            {
                const int tl  = tid & 63;
                const int bbp = tid >> 6;
                ull acc[8];
                #pragma unroll
                for (int d = 0; d < 8; d++) acc[d] = 0ull;
                const ull* __restrict__ hsr = hsb + bbp * BST + tl * ST;
                #pragma unroll 4
                for (int pp = 0; pp < NPAIR; pp++) {
                    ull hv = hsr[pp];
                    #pragma unroll
                    for (int d = 0; d < 8; d++)
                        acc[d] = f2fma(hv, wp2[d * NPAIR + pp], acc[d]);
                }
                float* xw = xp + bbp * XPS + (tbase + tl) * 8;
                #pragma unroll
                for (int d = 0; d < 8; d++) {
                    float ax, ay; f2unpack(acc[d], ax, ay);
                    xw[d] = xw[d] + ax + ay + bps[d];
                }
            }
            __syncthreads();
        }
    }

    if (tid < 32) {
        int bbi = tid >> 3, d = tid & 7;
        g_last[(b0 + bbi) * D_ + d] = xp[bbi * XPS + 511 * 8 + d];
    }
}

__global__ void finalize_kernel(const float* __restrict__ gamma,
                                const float* __restrict__ beta,
                                const float* __restrict__ wfc,
                                const float* __restrict__ bfc,
                                float* __restrict__ out)
{
    __shared__ float red[8][8];
    __shared__ float smu[8], svar[8];
    int b = threadIdx.x;
    int lane = b & 31, w = b >> 5;
    float v[8];
    #pragma unroll
    for (int d = 0; d < 8; d++) v[d] = g_last[b * 8 + d];

    #pragma unroll
    for (int d = 0; d < 8; d++) {
        float sv = v[d];
        #pragma unroll
        for (int o = 16; o > 0; o >>= 1) sv += __shfl_xor_sync(0xffffffffu, sv, o);
        if (lane == 0) red[d][w] = sv;
    }
    __syncthreads();
    if (b < 8) {
        float sv = 0.f;
        #pragma unroll
        for (int kk = 0; kk < 8; kk++) sv += red[b][kk];
        smu[b] = sv * (1.f / 256.f);
    }
    __syncthreads();
    float mu[8];
    #pragma unroll
    for (int d = 0; d < 8; d++) mu[d] = smu[d];
    __syncthreads();

    #pragma unroll
    for (int d = 0; d < 8; d++) {
        float dv = v[d] - mu[d];
        float sv = dv * dv;
        #pragma unroll
        for (int o = 16; o > 0; o >>= 1) sv += __shfl_xor_sync(0xffffffffu, sv, o);
        if (lane == 0) red[d][w] = sv;
    }
    __syncthreads();
    if (b < 8) {
        float sv = 0.f;
        #pragma unroll
        for (int kk = 0; kk < 8; kk++) sv += red[b][kk];
        svar[b] = sv * (1.f / 256.f);
    }
    __syncthreads();

    float acc = bfc[0];
    #pragma unroll
    for (int d = 0; d < 8; d++) {
        float bn = (v[d] - mu[d]) * rsqrtf(svar[d] + 1e-5f) * gamma[d] + beta[d];
        acc = fmaf(bn, wfc[d], acc);
    }
    out[b] = 1.f / (1.f + expf(-acc));
}

extern "C" void kernel_launch(void* const* d_in, const int* in_sizes, int n_in,
                              void* d_out, int out_size) {
    const float* X    = (const float*)d_in[0];
    const float* Wi   = (const float*)d_in[1];
    const float* Wf   = (const float*)d_in[2];
    const float* Wz   = (const float*)d_in[3];
    const float* Wo   = (const float*)d_in[4];
    const float* Ri   = (const float*)d_in[5];
    const float* Rf   = (const float*)d_in[6];
    const float* Rz   = (const float*)d_in[7];
    const float* Ro   = (const float*)d_in[8];
    const float* bi   = (const float*)d_in[9];
    const float* bf   = (const float*)d_in[10];
    const float* bz   = (const float*)d_in[11];
    const float* bo   = (const float*)d_in[12];
    const float* Wp   = (const float*)d_in[13];
    const float* bp   = (const float*)d_in[14];
    const float* gam  = (const float*)d_in[15];
    const float* bet  = (const float*)d_in[16];
    const float* Wfc  = (const float*)d_in[17];
    const float* bfc  = (const float*)d_in[18];

    cudaFuncSetAttribute(slstm_kernel,
                         cudaFuncAttributeMaxDynamicSharedMemorySize, SMEM_BYTES);
    slstm_kernel<<<64, 256, SMEM_BYTES>>>(X, Wi, Wf, Wz, Wo, Ri, Rf, Rz, Ro,
                                          bi, bf, bz, bo, Wp, bp);
    finalize_kernel<<<1, 256>>>(gam, bet, Wfc, bfc, (float*)d_out);
}

// round 9
// speedup vs baseline: 1.5884x; 1.5884x over previous
#include <cuda_runtime.h>

// sLSTM: B=256, T=512, D=8, H=120, L=4, NH=8, HD=15
// Warp-specialized producer/consumer, 128 CTAs x 256 threads (2 warps/SMSP):
//  - scan warps 0-3 (head k, 2 batches in lane halves, packed (j,j+60) f32x2):
//    per step only 4 preact LDS + 15 h LDS + 60 FFMA2 + cell. Ring h-exchange.
//  - producer warps 4-7 on the same SMSPs: precompute gate preactivations
//    (x@W^T+b, folded log2e/0.5) for chunk ch+1 into double-buffered smem,
//    and down-project chunk ch-1 (4 lanes/task + shfl reduce). Their issue
//    fills the scanner's serial-path stall cycles.
//  - chunk = 16 steps; hs ring = 64 rows (4 chunks) so projection reads
//    chunk ch-1 while scanner writes ch.

#define B_ 256
#define T_ 512
#define D_ 8
#define H_ 120
#define L_ 4
#define CH 16
#define NCH 32
#define PTT 480            // preact ull per step: 4 gates * 2 batches * 60
#define PBUF (CH * PTT)    // 7680
#define HBST (64 * 61 + 1) // hs batch stride (ull)
#define XPS 4100           // x batch stride (floats)
#define LOG2E 1.4426950408889634f

typedef unsigned long long ull;

__device__ float g_last[B_ * D_];

__device__ __forceinline__ ull f2pack(float x, float y) {
    ull r; asm("mov.b64 %0, {%1, %2};" : "=l"(r) : "f"(x), "f"(y)); return r;
}
__device__ __forceinline__ void f2unpack(ull v, float& x, float& y) {
    asm("mov.b64 {%0, %1}, %2;" : "=f"(x), "=f"(y) : "l"(v));
}
__device__ __forceinline__ ull f2fma(ull a, ull b, ull c) {
    ull d; asm("fma.rn.f32x2 %0, %1, %2, %3;" : "=l"(d) : "l"(a), "l"(b), "l"(c));
    return d;
}
__device__ __forceinline__ ull f2add(ull a, ull b) {
    ull d; asm("add.rn.f32x2 %0, %1, %2;" : "=l"(d) : "l"(a), "l"(b));
    return d;
}
__device__ __forceinline__ float tanh_ap(float x) {
    float r; asm("tanh.approx.f32 %0, %1;" : "=f"(r) : "f"(x)); return r;
}
__device__ __forceinline__ float rcp_ap(float x) {
    float r; asm("rcp.approx.f32 %0, %1;" : "=f"(r) : "f"(x)); return r;
}
__device__ __forceinline__ float ex2_ap(float x) {
    float r; asm("ex2.approx.f32 %0, %1;" : "=f"(r) : "f"(x)); return r;
}

// sLSTM cell. it/ft pre-scaled by log2e, ot pre-scaled by 0.5.
__device__ __forceinline__ float cellf(float it, float ft, float zt, float ot,
                                       float& c, float& nn, float& m) {
    float z  = tanh_ap(zt);
    float o  = fmaf(tanh_ap(ot), 0.5f, 0.5f);
    float b  = ft + m;
    float mn = fmaxf(it, b);
    float e  = ex2_ap(-fabsf(it - b));
    bool ag  = (it >= b);
    float ip = ag ? 1.f : e;
    float fp = ag ? e : 1.f;
    c  = fp * c  + ip * z;
    nn = fp * nn + ip;
    m  = mn;
    return o * c * rcp_ap(nn);
}

// shared layout (ull units):
//   pre  [2][CH][4][2][60] = 15360   preact double buffer
//   hsb  [2][64][61]+pad   = 7810    h history ring (paired)
//   wpT  [60][8]           = 480     Wp transposed pairs
//   bps  [8 floats]        = 4
//   xp   [2][XPS] floats   = 4100    residual/x stream (plain f32)
#define SM_PRE 0
#define SM_HS  15360
#define SM_WPT (SM_HS + 2 * HBST)
#define SM_BPS (SM_WPT + 480)
#define SM_XP  (SM_BPS + 4)
#define SM_TOT (SM_XP + 4100)
#define SMEM_BYTES (SM_TOT * 8 + 16)

__global__ void __launch_bounds__(256, 1) slstm_kernel(
    const float* __restrict__ X,
    const float* __restrict__ Wi, const float* __restrict__ Wf,
    const float* __restrict__ Wz, const float* __restrict__ Wo,
    const float* __restrict__ Ri, const float* __restrict__ Rf,
    const float* __restrict__ Rz, const float* __restrict__ Ro,
    const float* __restrict__ bi, const float* __restrict__ bf,
    const float* __restrict__ bz, const float* __restrict__ bo,
    const float* __restrict__ Wp, const float* __restrict__ bp)
{
    extern __shared__ ull sm[];
    ull* pre  = sm + SM_PRE;
    ull* hsb  = sm + SM_HS;
    ull* wpT  = sm + SM_WPT;
    float* bps = (float*)(sm + SM_BPS);
    float* xp  = (float*)(sm + SM_XP);

    const int tid  = threadIdx.x;
    const int lane = tid & 31;
    const int wid  = tid >> 5;
    const bool isScan = (wid < 4);
    const int k    = wid & 3;            // scan: head block; prod: slot group
    const int half = (lane >> 4) & 1;    // batch within CTA
    const int e    = lane & 15;
    const bool act = (e < 15);
    const int ec   = act ? e : 14;
    const int slot = k * 15 + ec;        // 0..59
    const int b0   = blockIdx.x * 2;

    // load input x (plain float) for 2 batches
    for (int idx = tid; idx < 2 * T_ * D_; idx += 256) {
        int bbi = idx >> 12;
        int i   = idx & 4095;
        xp[bbi * XPS + i] = X[(b0 + bbi) * (T_ * D_) + i];
    }

    #pragma unroll 1
    for (int l = 0; l < L_; l++) {
        // ---- per-role weights into registers ----
        ull rIv[15], rFv[15], rZv[15], rOv[15];          // scan only
        ull wIv[8],  wFv[8],  wZv[8],  wOv[8];           // producer only
        ull bIv = 0, bFv = 0, bZv = 0, bOv = 0;          // producer only
        if (isScan) {
            const float* ri = Ri + l * 8 * 225;
            const float* rf = Rf + l * 8 * 225;
            const float* rz = Rz + l * 8 * 225;
            const float* ro = Ro + l * 8 * 225;
            #pragma unroll
            for (int d = 0; d < 15; d++) {
                int i0 = k * 225 + d * 15 + ec;
                int i1 = (k + 4) * 225 + d * 15 + ec;
                rIv[d] = f2pack(LOG2E * ri[i0], LOG2E * ri[i1]);
                rFv[d] = f2pack(LOG2E * rf[i0], LOG2E * rf[i1]);
                rZv[d] = f2pack(rz[i0], rz[i1]);
                rOv[d] = f2pack(0.5f * ro[i0], 0.5f * ro[i1]);
            }
            // zero hs row 63 ("step -1") for both batches
            if (act) {
                hsb[0 * HBST + 63 * 61 + slot] = 0ull;
                hsb[1 * HBST + 63 * 61 + slot] = 0ull;
            }
        } else {
            const int j0 = slot, j1 = slot + 60;
            const float* wi = Wi + l * H_ * D_;
            const float* wf = Wf + l * H_ * D_;
            const float* wz = Wz + l * H_ * D_;
            const float* wo = Wo + l * H_ * D_;
            #pragma unroll
            for (int d = 0; d < 8; d++) {
                wIv[d] = f2pack(LOG2E * wi[j0 * 8 + d], LOG2E * wi[j1 * 8 + d]);
                wFv[d] = f2pack(LOG2E * wf[j0 * 8 + d], LOG2E * wf[j1 * 8 + d]);
                wZv[d] = f2pack(wz[j0 * 8 + d], wz[j1 * 8 + d]);
                wOv[d] = f2pack(0.5f * wo[j0 * 8 + d], 0.5f * wo[j1 * 8 + d]);
            }
            bIv = f2pack(LOG2E * bi[l * H_ + j0], LOG2E * bi[l * H_ + j1]);
            bFv = f2pack(LOG2E * bf[l * H_ + j0], LOG2E * bf[l * H_ + j1]);
            bZv = f2pack(bz[l * H_ + j0], bz[l * H_ + j1]);
            bOv = f2pack(0.5f * bo[l * H_ + j0], 0.5f * bo[l * H_ + j1]);
        }
        // wpT pairs + bp (cooperative)
        for (int idx = tid; idx < 480; idx += 256) {
            int pp = idx >> 3, d = idx & 7;
            const float* wp = Wp + l * D_ * H_;
            wpT[idx] = f2pack(wp[d * H_ + pp], wp[d * H_ + 60 + pp]);
        }
        if (tid < 8) bps[tid] = bp[l * D_ + tid];
        __syncthreads();

        float c0 = 0.f, c1 = 0.f, n0 = 0.f, n1 = 0.f, m0 = 0.f, m1 = 0.f;

        #pragma unroll 1
        for (int ch = -1; ch < NCH; ch++) {
            if (isScan) {
                if (ch >= 0) {
                    const ull* __restrict__ prb =
                        pre + (ch & 1) * PBUF + half * 60 + slot;
                    ull* __restrict__ hrow = hsb + half * HBST;
                    const int hoff = k * 15;
                    #pragma unroll 2
                    for (int tt = 0; tt < CH; tt++) {
                        const int t = ch * CH + tt;
                        const int row = t & 63;
                        const int prow = (t - 1) & 63;
                        const ull* pr = prb + tt * PTT;
                        ull aI = pr[0], aF = pr[120], aZ = pr[240], aO = pr[360];
                        const ull* __restrict__ hr = hrow + prow * 61 + hoff;
                        #pragma unroll
                        for (int d = 0; d < 15; d++) {
                            ull hv = hr[d];
                            aI = f2fma(hv, rIv[d], aI);
                            aF = f2fma(hv, rFv[d], aF);
                            aZ = f2fma(hv, rZv[d], aZ);
                            aO = f2fma(hv, rOv[d], aO);
                        }
                        float itx, ity, ftx, fty, ztx, zty, otx, oty;
                        f2unpack(aI, itx, ity); f2unpack(aF, ftx, fty);
                        f2unpack(aZ, ztx, zty); f2unpack(aO, otx, oty);
                        float h0 = cellf(itx, ftx, ztx, otx, c0, n0, m0);
                        float h1 = cellf(ity, fty, zty, oty, c1, n1, m1);
                        if (act)
                            hrow[row * 61 + slot] = f2pack(h0, h1);
                    }
                }
            } else {
                // ---- producer: preact for chunk ch+1 ----
                if (ch + 1 < NCH) {
                    const int tb = (ch + 1) * CH;
                    ull* __restrict__ prw =
                        pre + ((ch + 1) & 1) * PBUF + half * 60 + slot;
                    const float* __restrict__ xr0 = xp + half * XPS + tb * 8;
                    #pragma unroll 2
                    for (int tt = 0; tt < CH; tt++) {
                        const float* xr = xr0 + tt * 8;
                        ull aI = bIv, aF = bFv, aZ = bZv, aO = bOv;
                        #pragma unroll
                        for (int d = 0; d < 8; d++) {
                            float v = xr[d];
                            ull xv = f2pack(v, v);
                            aI = f2fma(xv, wIv[d], aI);
                            aF = f2fma(xv, wFv[d], aF);
                            aZ = f2fma(xv, wZv[d], aZ);
                            aO = f2fma(xv, wOv[d], aO);
                        }
                        if (act) {
                            ull* pw = prw + tt * PTT;
                            pw[0] = aI; pw[120] = aF; pw[240] = aZ; pw[360] = aO;
                        }
                    }
                }
                // ---- producer: projection of chunk ch-1 ----
                if (ch >= 1) {
                    const int c = ch - 1;
                    const int task = k * 8 + (lane >> 2);  // 0..31
                    const int part = lane & 3;
                    const int bbp  = task >> 4;
                    const int tl   = task & 15;
                    const int t    = c * CH + tl;
                    const int row  = t & 63;
                    const ull* __restrict__ hsr =
                        hsb + bbp * HBST + row * 61 + part * 15;
                    const ull* __restrict__ wv = wpT + part * 15 * 8;
                    ull acc[8];
                    #pragma unroll
                    for (int d = 0; d < 8; d++) acc[d] = 0ull;
                    #pragma unroll
                    for (int j = 0; j < 15; j++) {
                        ull hv = hsr[j];
                        #pragma unroll
                        for (int d = 0; d < 8; d++)
                            acc[d] = f2fma(hv, wv[j * 8 + d], acc[d]);
                    }
                    #pragma unroll
                    for (int off = 1; off <= 2; off <<= 1) {
                        #pragma unroll
                        for (int d = 0; d < 8; d++) {
                            ull o = __shfl_xor_sync(0xffffffffu, acc[d], off);
                            acc[d] = f2add(acc[d], o);
                        }
                    }
                    if (part == 0) {
                        float* xw = xp + bbp * XPS + t * 8;
                        #pragma unroll
                        for (int d = 0; d < 8; d++) {
                            float lo, hi; f2unpack(acc[d], lo, hi);
                            xw[d] += lo + hi + bps[d];
                        }
                    }
                }
            }
            __syncthreads();
        }
        // ---- final projection: chunk 31 ----
        if (!isScan) {
            const int c = NCH - 1;
            const int task = k * 8 + (lane >> 2);
            const int part = lane & 3;
            const int bbp  = task >> 4;
            const int tl   = task & 15;
            const int t    = c * CH + tl;
            const int row  = t & 63;
            const ull* __restrict__ hsr = hsb + bbp * HBST + row * 61 + part * 15;
            const ull* __restrict__ wv = wpT + part * 15 * 8;
            ull acc[8];
            #pragma unroll
            for (int d = 0; d < 8; d++) acc[d] = 0ull;
            #pragma unroll
            for (int j = 0; j < 15; j++) {
                ull hv = hsr[j];
                #pragma unroll
                for (int d = 0; d < 8; d++)
                    acc[d] = f2fma(hv, wv[j * 8 + d], acc[d]);
            }
            #pragma unroll
            for (int off = 1; off <= 2; off <<= 1) {
                #pragma unroll
                for (int d = 0; d < 8; d++) {
                    ull o = __shfl_xor_sync(0xffffffffu, acc[d], off);
                    acc[d] = f2add(acc[d], o);
                }
            }
            if (part == 0) {
                float* xw = xp + bbp * XPS + t * 8;
                #pragma unroll
                for (int d = 0; d < 8; d++) {
                    float lo, hi; f2unpack(acc[d], lo, hi);
                    xw[d] += lo + hi + bps[d];
                }
            }
        }
        __syncthreads();
    }

    if (tid < 16) {
        int bbi = tid >> 3, d = tid & 7;
        g_last[(b0 + bbi) * D_ + d] = xp[bbi * XPS + 511 * 8 + d];
    }
}

__global__ void finalize_kernel(const float* __restrict__ gamma,
                                const float* __restrict__ beta,
                                const float* __restrict__ wfc,
                                const float* __restrict__ bfc,
                                float* __restrict__ out)
{
    __shared__ float red[8][8];
    __shared__ float smu[8], svar[8];
    int b = threadIdx.x;
    int lane = b & 31, w = b >> 5;
    float v[8];
    #pragma unroll
    for (int d = 0; d < 8; d++) v[d] = g_last[b * 8 + d];

    #pragma unroll
    for (int d = 0; d < 8; d++) {
        float sv = v[d];
        #pragma unroll
        for (int o = 16; o > 0; o >>= 1) sv += __shfl_xor_sync(0xffffffffu, sv, o);
        if (lane == 0) red[d][w] = sv;
    }
    __syncthreads();
    if (b < 8) {
        float sv = 0.f;
        #pragma unroll
        for (int kk = 0; kk < 8; kk++) sv += red[b][kk];
        smu[b] = sv * (1.f / 256.f);
    }
    __syncthreads();
    float mu[8];
    #pragma unroll
    for (int d = 0; d < 8; d++) mu[d] = smu[d];
    __syncthreads();

    #pragma unroll
    for (int d = 0; d < 8; d++) {
        float dv = v[d] - mu[d];
        float sv = dv * dv;
        #pragma unroll
        for (int o = 16; o > 0; o >>= 1) sv += __shfl_xor_sync(0xffffffffu, sv, o);
        if (lane == 0) red[d][w] = sv;
    }
    __syncthreads();
    if (b < 8) {
        float sv = 0.f;
        #pragma unroll
        for (int kk = 0; kk < 8; kk++) sv += red[b][kk];
        svar[b] = sv * (1.f / 256.f);
    }
    __syncthreads();

    float acc = bfc[0];
    #pragma unroll
    for (int d = 0; d < 8; d++) {
        float bn = (v[d] - mu[d]) * rsqrtf(svar[d] + 1e-5f) * gamma[d] + beta[d];
        acc = fmaf(bn, wfc[d], acc);
    }
    out[b] = 1.f / (1.f + expf(-acc));
}

extern "C" void kernel_launch(void* const* d_in, const int* in_sizes, int n_in,
                              void* d_out, int out_size) {
    const float* X    = (const float*)d_in[0];
    const float* Wi   = (const float*)d_in[1];
    const float* Wf   = (const float*)d_in[2];
    const float* Wz   = (const float*)d_in[3];
    const float* Wo   = (const float*)d_in[4];
    const float* Ri   = (const float*)d_in[5];
    const float* Rf   = (const float*)d_in[6];
    const float* Rz   = (const float*)d_in[7];
    const float* Ro   = (const float*)d_in[8];
    const float* bi   = (const float*)d_in[9];
    const float* bf   = (const float*)d_in[10];
    const float* bz   = (const float*)d_in[11];
    const float* bo   = (const float*)d_in[12];
    const float* Wp   = (const float*)d_in[13];
    const float* bp   = (const float*)d_in[14];
    const float* gam  = (const float*)d_in[15];
    const float* bet  = (const float*)d_in[16];
    const float* Wfc  = (const float*)d_in[17];
    const float* bfc  = (const float*)d_in[18];

    cudaFuncSetAttribute(slstm_kernel,
                         cudaFuncAttributeMaxDynamicSharedMemorySize, SMEM_BYTES);
    slstm_kernel<<<128, 256, SMEM_BYTES>>>(X, Wi, Wf, Wz, Wo, Ri, Rf, Rz, Ro,
                                           bi, bf, bz, bo, Wp, bp);
    finalize_kernel<<<1, 256>>>(gam, bet, Wfc, bfc, (float*)d_out);
}